// round 15
// baseline (speedup 1.0000x reference)
#include <cuda_runtime.h>
#include <cuda_fp16.h>
#include <cstdint>
#include <math.h>

#define N_NODES 50000
#define N_EDGES 800000
#define OBS_DIM 128
#define H_DIM   128
#define ENC_H   512
#define OUT_LD  384
#define NB_SCAN 196
#define NB_SCAT 3125
#define MT      391            // full row tiles
#define MT_H1   196            // rows [0, 25088)
#define MT_H2   195            // rows [25088, 50000)
#define SPLIT   25088
#define G1_EXTRA 3509          // 256 W2 + 64 qkv1 + 64 qkv2 + 3125 count
#define GAT_H1_BLOCKS 3136     // 25088/8
#define GAT_H2_BLOCKS 3114     // ceil(24912/8)
#define GAT_FULL_BLOCKS 6250

// ---------------- scratch ------------------------------------------------------
__device__ __half   g_obsT[(size_t)N_NODES * OBS_DIM];
__device__ __half   g_h1[(size_t)N_NODES * ENC_H];
__device__ __half   g_xt[(size_t)N_NODES * H_DIM];
__device__ float    g_q [(size_t)N_NODES * H_DIM];
__device__ __half   g_kv[(size_t)N_NODES * 256];
__device__ __half   g_W1t[512 * 128];
__device__ __half   g_W2t[128 * 512];
__device__ __half   g_Wt1[384 * 128];
__device__ __half   g_Wt2[384 * 128];
__device__ float    g_bp1[384];
__device__ float    g_bp2[384];
__device__ int      g_deg[N_NODES];
__device__ int      g_off[N_NODES + 1];
__device__ int      g_pos[N_NODES];
__device__ int      g_srcs[N_EDGES];
__device__ unsigned long long g_lb[NB_SCAN];

#define LB_PARTIAL (1ull << 62)
#define LB_PREFIX  (2ull << 62)
#define LB_MASK    (3ull << 62)

struct WPtrs {
    const float *W2;
    const float *Wq1, *bq1, *Wk1, *bk1, *Wv1, *bv1;
    const float *Wq2, *bq2, *Wk2, *bk2, *Wv2, *bv2;
    const int *src, *dst;
};

// ---------------- helpers ------------------------------------------------------
__device__ __forceinline__ uint32_t smem_u32(const void* p) {
    uint32_t a;
    asm("{ .reg .u64 t; cvta.to.shared.u64 t, %1; cvt.u32.u64 %0, t; }" : "=r"(a) : "l"(p));
    return a;
}
__device__ __forceinline__ void cp16(uint32_t sm_addr, const void* g, int nbytes) {
    asm volatile("cp.async.cg.shared.global [%0], [%1], 16, %2;"
                 :: "r"(sm_addr), "l"(g), "r"(nbytes) : "memory");
}
__device__ __forceinline__ void cp_commit() {
    asm volatile("cp.async.commit_group;" ::: "memory");
}
template <int N>
__device__ __forceinline__ void cp_wait() {
    asm volatile("cp.async.wait_group %0;" :: "n"(N) : "memory");
}
__device__ __forceinline__ void mma_f16(float* c, const uint32_t* a, const uint32_t* b) {
    asm volatile(
        "mma.sync.aligned.m16n8k16.row.col.f32.f16.f16.f32 "
        "{%0,%1,%2,%3}, {%4,%5,%6,%7}, {%8,%9}, {%0,%1,%2,%3};\n"
        : "+f"(c[0]), "+f"(c[1]), "+f"(c[2]), "+f"(c[3])
        : "r"(a[0]), "r"(a[1]), "r"(a[2]), "r"(a[3]), "r"(b[0]), "r"(b[1]));
}
__device__ __forceinline__ void ldsm_x4(uint32_t& r0, uint32_t& r1, uint32_t& r2, uint32_t& r3,
                                        uint32_t addr) {
    asm volatile("ldmatrix.sync.aligned.m8n8.x4.shared.b16 {%0,%1,%2,%3}, [%4];"
                 : "=r"(r0), "=r"(r1), "=r"(r2), "=r"(r3) : "r"(addr));
}

// ---------------- CSR / prep helper blocks --------------------------------------
__device__ __forceinline__ int block_excl_scan(int v, int tid) {
    int lane = tid & 31, w = tid >> 5;
    int x = v;
    #pragma unroll
    for (int d = 1; d < 32; d <<= 1) {
        int t = __shfl_up_sync(0xffffffffu, x, d);
        if (lane >= d) x += t;
    }
    __shared__ int ws[8];
    if (lane == 31) ws[w] = x;
    __syncthreads();
    if (w == 0) {
        int y = (lane < 8) ? ws[lane] : 0;
        #pragma unroll
        for (int d = 1; d < 8; d <<= 1) {
            int t = __shfl_up_sync(0xffffffffu, y, d);
            if (lane >= d) y += t;
        }
        if (lane < 8) ws[lane] = y;
    }
    __syncthreads();
    return x - v + ((w > 0) ? ws[w - 1] : 0);
}

__device__ __forceinline__ void prepB_block_fn(int b, const WPtrs& wp) {
    int t = threadIdx.x;
    if (b < 256) {
        int i = b * 256 + t;
        int k = i >> 7, n = i & 127;
        g_W2t[n * 512 + k] = __float2half_rn(wp.W2[i]);
    } else if (b < 320) {
        int i = (b - 256) * 256 + t;
        int k = i >> 7, n = i & 127;
        g_Wt1[n * 128 + k]         = __float2half_rn(wp.Wq1[i]);
        g_Wt1[(n + 128) * 128 + k] = __float2half_rn(wp.Wk1[i]);
        g_Wt1[(n + 256) * 128 + k] = __float2half_rn(wp.Wv1[i]);
        if (i < 128) { g_bp1[i] = wp.bq1[i]; g_bp1[128 + i] = wp.bk1[i]; g_bp1[256 + i] = wp.bv1[i]; }
    } else if (b < 384) {
        int i = (b - 320) * 256 + t;
        int k = i >> 7, n = i & 127;
        g_Wt2[n * 128 + k]         = __float2half_rn(wp.Wq2[i]);
        g_Wt2[(n + 128) * 128 + k] = __float2half_rn(wp.Wk2[i]);
        g_Wt2[(n + 256) * 128 + k] = __float2half_rn(wp.Wv2[i]);
        if (i < 128) { g_bp2[i] = wp.bq2[i]; g_bp2[128 + i] = wp.bk2[i]; g_bp2[256 + i] = wp.bv2[i]; }
    } else {
        int e = (b - 384) * 256 + t;
        if (e < N_EDGES) atomicAdd(&g_deg[wp.dst[e]], 1);
    }
}

__device__ __forceinline__ void scan_block_fn(int b) {
    int tid = threadIdx.x;
    int i = b * 256 + tid;
    int v = (i < N_NODES) ? g_deg[i] : 0;
    if (i < N_NODES) g_deg[i] = 0;
    int excl = block_excl_scan(v, tid);
    __shared__ int s_prefix;

    if (tid == 255) {
        unsigned long long agg = (unsigned long long)(excl + v);
        if (b == 0) atomicExch(&g_lb[0], LB_PREFIX | agg);
        else        atomicExch(&g_lb[b], LB_PARTIAL | agg);
    }
    if (tid == 0) {
        if (b == 0) s_prefix = 0;
        else {
            long long running = 0;
            int p = b - 1;
            for (;;) {
                unsigned long long x = atomicAdd(&g_lb[p], 0ull);
                unsigned long long st = x & LB_MASK;
                if (st == LB_PREFIX)  { running += (long long)(x & ~LB_MASK); break; }
                if (st == LB_PARTIAL) { running += (long long)(x & ~LB_MASK); p--; }
            }
            s_prefix = (int)running;
        }
    }
    __syncthreads();
    int pre = s_prefix;
    if (b > 0 && tid == 255)
        atomicExch(&g_lb[b], LB_PREFIX | (unsigned long long)(pre + excl + v));
    if (i < N_NODES) {
        int o = pre + excl;
        g_off[i] = o;
        g_pos[i] = o;
    }
    if (b == NB_SCAN - 1 && tid == 255) g_off[N_NODES] = pre + excl + v;
}

__device__ __forceinline__ void scatter_block_fn(int b, const WPtrs& wp) {
    int e = b * 256 + threadIdx.x;
    if (e < NB_SCAN) g_lb[e] = 0ull;
    if (e < N_EDGES) {
        int d = wp.dst[e];
        int idx = atomicAdd(&g_pos[d], 1);
        g_srcs[idx] = wp.src[e];
    }
}

// ---------------- K=128 GEMM body (128x128 tile) --------------------------------
#define K128_SROW 272
#define K128_OP   (128 * K128_SROW)
#define K128_SMEM (2 * K128_OP)       // 69632

template <int MODE>
__device__ __forceinline__ void gemm128_body(
    int gb, int mtLocal, int rowOff,
    const __half* __restrict__ A, int lda,
    const __half* __restrict__ Bt,
    const float* __restrict__ bias,
    __half* __restrict__ Ct, int ldct, int M, char* sm)
{
    const uint32_t sbase = smem_u32(sm);
    const int tid  = threadIdx.x;
    const int lane = tid & 31;
    const int w    = tid >> 5;
    const int gid  = lane >> 2;
    const int tig  = lane & 3;
    const int warpM = w >> 2;
    const int warpN = w & 3;
    const int rowBase = rowOff + (gb % mtLocal) * 128;
    const int colBase = (gb / mtLocal) * 128;

    #pragma unroll
    for (int p = 0; p < 8; p++) {
        int idx = tid + (p << 8);
        int row = idx >> 4;
        int ch  = idx & 15;
        uint32_t off = row * K128_SROW + (ch << 4);
        int gr = rowBase + row;
        int okA = (gr < M) ? 16 : 0;
        cp16(sbase + off, A + (size_t)(okA ? gr : 0) * lda + ch * 8, okA);
        cp16(sbase + K128_OP + off, Bt + (size_t)(colBase + row) * 128 + ch * 8, 16);
    }
    cp_commit();

    const int sub = lane >> 3, lr = lane & 7;
    const uint32_t aOff = (uint32_t)(warpM * 64 + ((sub & 1) << 3) + lr) * K128_SROW
                        + ((uint32_t)(sub >> 1) << 4);
    const uint32_t bOff = K128_OP
                        + (uint32_t)(warpN * 32 + ((sub >> 1) << 3) + lr) * K128_SROW
                        + ((uint32_t)(sub & 1) << 4);

    float acc[4][4][4];
    #pragma unroll
    for (int mt = 0; mt < 4; mt++)
        #pragma unroll
        for (int nt = 0; nt < 4; nt++)
            #pragma unroll
            for (int j = 0; j < 4; j++) acc[mt][nt][j] = 0.f;

    cp_wait<0>();
    __syncthreads();

    #pragma unroll
    for (int kk = 0; kk < 8; kk++) {
        const uint32_t kb = (uint32_t)kk << 5;
        uint32_t af[4][4], bf[4][2];
        #pragma unroll
        for (int mt = 0; mt < 4; mt++)
            ldsm_x4(af[mt][0], af[mt][1], af[mt][2], af[mt][3],
                    sbase + aOff + (uint32_t)(mt * 16) * K128_SROW + kb);
        #pragma unroll
        for (int p = 0; p < 2; p++)
            ldsm_x4(bf[2 * p][0], bf[2 * p][1], bf[2 * p + 1][0], bf[2 * p + 1][1],
                    sbase + bOff + (uint32_t)(p * 16) * K128_SROW + kb);
        #pragma unroll
        for (int mt = 0; mt < 4; mt++)
            #pragma unroll
            for (int nt = 0; nt < 4; nt++)
                mma_f16(acc[mt][nt], af[mt], bf[nt]);
    }

    #pragma unroll
    for (int mt = 0; mt < 4; mt++) {
        int r0 = rowBase + warpM * 64 + mt * 16 + gid;
        #pragma unroll
        for (int nt = 0; nt < 4; nt++) {
            int cc = colBase + warpN * 32 + nt * 8 + tig * 2;
            float2 bi = *reinterpret_cast<const float2*>(bias + cc);
            #pragma unroll
            for (int h = 0; h < 2; h++) {
                int r = r0 + h * 8;
                if (r < M) {
                    float ox = acc[mt][nt][h * 2 + 0] + bi.x;
                    float oy = acc[mt][nt][h * 2 + 1] + bi.y;
                    if (MODE == 0) {
                        ox = fmaxf(ox, 0.f); oy = fmaxf(oy, 0.f);
                        *reinterpret_cast<__half2*>(Ct + (size_t)r * ldct + cc) =
                            __floats2half2_rn(ox, oy);
                    } else {
                        if (colBase == 0) {
                            *reinterpret_cast<float2*>(g_q + (size_t)r * H_DIM + cc) =
                                make_float2(ox, oy);
                        } else {
                            *reinterpret_cast<__half2*>(g_kv + (size_t)r * 256 + (cc - 128)) =
                                __floats2half2_rn(ox, oy);
                        }
                    }
                }
            }
        }
    }
}

// ---------------- K=512 GEMM body (3-stage pipeline) ----------------------------
#define SROW_B   80
#define ST_OP_B  (128 * SROW_B)
#define ST_BYTES (2 * ST_OP_B)
#define G512_SMEM (3 * ST_BYTES)      // 61440

__device__ __forceinline__ void load_stage512(
    uint32_t sbase, int stage, const __half* __restrict__ A,
    const __half* __restrict__ Bt, int rowBase, int k0, int M, int tid)
{
    uint32_t st = sbase + stage * ST_BYTES;
    #pragma unroll
    for (int p = 0; p < 2; p++) {
        int idx = tid + (p << 8);
        int row = idx >> 2;
        int kc  = idx & 3;
        uint32_t off = row * SROW_B + kc * 16;
        int gr = rowBase + row;
        int okA = (gr < M) ? 16 : 0;
        cp16(st + off, A + (size_t)(okA ? gr : 0) * ENC_H + k0 + kc * 8, okA);
        cp16(st + ST_OP_B + off, Bt + (size_t)row * ENC_H + k0 + kc * 8, 16);
    }
    cp_commit();
}

__device__ __forceinline__ void gemm512_body(
    int rowTile, int rowOff,
    const __half* __restrict__ A,
    const __half* __restrict__ Bt,
    const float* __restrict__ bias,
    float* __restrict__ C, int ldc,
    __half* __restrict__ Ct, int ldct, int M, char* sm)
{
    const uint32_t sbase = smem_u32(sm);
    const int tid  = threadIdx.x;
    const int lane = tid & 31;
    const int w    = tid >> 5;
    const int gid  = lane >> 2;
    const int tig  = lane & 3;
    const int warpM = w >> 2;
    const int warpN = w & 3;
    const int rowBase = rowOff + rowTile * 128;
    const int nCh = ENC_H >> 5;   // 16

    const int sub = lane >> 3, lr = lane & 7;
    const uint32_t aOff = (uint32_t)(warpM * 64 + ((sub & 1) << 3) + lr) * SROW_B
                        + ((uint32_t)(sub >> 1) << 4);
    const uint32_t bOff = ST_OP_B
                        + (uint32_t)(warpN * 32 + ((sub >> 1) << 3) + lr) * SROW_B
                        + ((uint32_t)(sub & 1) << 4);

    float acc[4][4][4];
    #pragma unroll
    for (int mt = 0; mt < 4; mt++)
        #pragma unroll
        for (int nt = 0; nt < 4; nt++)
            #pragma unroll
            for (int j = 0; j < 4; j++) acc[mt][nt][j] = 0.f;

    load_stage512(sbase, 0, A, Bt, rowBase, 0, M, tid);
    load_stage512(sbase, 1, A, Bt, rowBase, 32, M, tid);

    int stage = 0;
    #pragma unroll 1
    for (int c = 0; c < nCh; c++) {
        if (c + 1 < nCh) cp_wait<1>(); else cp_wait<0>();
        __syncthreads();
        if (c + 2 < nCh) {
            int ns = stage + 2; if (ns >= 3) ns -= 3;
            load_stage512(sbase, ns, A, Bt, rowBase, (c + 2) << 5, M, tid);
        }
        const uint32_t stA = sbase + stage * ST_BYTES;
        #pragma unroll
        for (int kk = 0; kk < 2; kk++) {
            const uint32_t kb = (uint32_t)kk << 5;
            uint32_t af[4][4], bf[4][2];
            #pragma unroll
            for (int mt = 0; mt < 4; mt++)
                ldsm_x4(af[mt][0], af[mt][1], af[mt][2], af[mt][3],
                        stA + aOff + (uint32_t)(mt * 16) * SROW_B + kb);
            #pragma unroll
            for (int p = 0; p < 2; p++)
                ldsm_x4(bf[2 * p][0], bf[2 * p][1], bf[2 * p + 1][0], bf[2 * p + 1][1],
                        stA + bOff + (uint32_t)(p * 16) * SROW_B + kb);
            #pragma unroll
            for (int mt = 0; mt < 4; mt++)
                #pragma unroll
                for (int nt = 0; nt < 4; nt++)
                    mma_f16(acc[mt][nt], af[mt], bf[nt]);
        }
        stage++; if (stage >= 3) stage = 0;
    }

    #pragma unroll
    for (int mt = 0; mt < 4; mt++) {
        int r0 = rowBase + warpM * 64 + mt * 16 + gid;
        #pragma unroll
        for (int nt = 0; nt < 4; nt++) {
            int cc = warpN * 32 + nt * 8 + tig * 2;
            float2 bi = *reinterpret_cast<const float2*>(bias + cc);
            #pragma unroll
            for (int h = 0; h < 2; h++) {
                int r = r0 + h * 8;
                if (r < M) {
                    float ox = fmaxf(acc[mt][nt][h * 2 + 0] + bi.x, 0.f);
                    float oy = fmaxf(acc[mt][nt][h * 2 + 1] + bi.y, 0.f);
                    *reinterpret_cast<float2*>(C + (size_t)r * ldc + cc) = make_float2(ox, oy);
                    *reinterpret_cast<__half2*>(Ct + (size_t)r * ldct + cc) =
                        __floats2half2_rn(ox, oy);
                }
            }
        }
    }
}

// ---------------- GAT body ------------------------------------------------------
template <bool WXT>
__device__ __forceinline__ void gat_body(int node, int lane, float* __restrict__ zout, int ldz)
{
    const float4 qv = *reinterpret_cast<const float4*>(g_q + (size_t)node * H_DIM + lane * 4);

    float mA = -1e30f, sA = 0.f, axA = 0.f, ayA = 0.f, azA = 0.f, awA = 0.f;
    float mB = -1e30f, sB = 0.f, axB = 0.f, ayB = 0.f, azB = 0.f, awB = 0.f;

    int t = g_off[node], end = g_off[node + 1];
    while (t < end) {
        int nload = min(32, end - t);
        int sj = (lane < nload) ? __ldg(&g_srcs[t + lane]) : 0;
        int j = 0;
        for (; j + 1 < nload; j += 2) {
            int s0 = __shfl_sync(0xffffffffu, sj, j);
            int s1 = __shfl_sync(0xffffffffu, sj, j + 1);
            const uint2* kv0 = reinterpret_cast<const uint2*>(g_kv + (size_t)s0 * 256);
            const uint2* kv1 = reinterpret_cast<const uint2*>(g_kv + (size_t)s1 * 256);
            uint2 k0u = kv0[lane],      k1u = kv1[lane];
            uint2 v0u = kv0[32 + lane], v1u = kv1[32 + lane];

            float2 k0a = __half22float2(*reinterpret_cast<__half2*>(&k0u.x));
            float2 k0b = __half22float2(*reinterpret_cast<__half2*>(&k0u.y));
            float2 k1a = __half22float2(*reinterpret_cast<__half2*>(&k1u.x));
            float2 k1b = __half22float2(*reinterpret_cast<__half2*>(&k1u.y));

            float p0 = qv.x * k0a.x + qv.y * k0a.y + qv.z * k0b.x + qv.w * k0b.y;
            float p1 = qv.x * k1a.x + qv.y * k1a.y + qv.z * k1b.x + qv.w * k1b.y;
            p0 += __shfl_xor_sync(0xffffffffu, p0, 1);
            p1 += __shfl_xor_sync(0xffffffffu, p1, 1);
            p0 += __shfl_xor_sync(0xffffffffu, p0, 2);
            p1 += __shfl_xor_sync(0xffffffffu, p1, 2);
            float sc0 = p0 * 0.25f, sc1 = p1 * 0.25f;

            float2 v0a = __half22float2(*reinterpret_cast<__half2*>(&v0u.x));
            float2 v0b = __half22float2(*reinterpret_cast<__half2*>(&v0u.y));
            float2 v1a = __half22float2(*reinterpret_cast<__half2*>(&v1u.x));
            float2 v1b = __half22float2(*reinterpret_cast<__half2*>(&v1u.y));

            float mn0 = fmaxf(mA, sc0);
            float mn1 = fmaxf(mB, sc1);
            float c0 = __expf(mA - mn0), w0 = __expf(sc0 - mn0);
            float c1 = __expf(mB - mn1), w1 = __expf(sc1 - mn1);
            sA = sA * c0 + w0;
            sB = sB * c1 + w1;
            axA = axA * c0 + w0 * v0a.x;  axB = axB * c1 + w1 * v1a.x;
            ayA = ayA * c0 + w0 * v0a.y;  ayB = ayB * c1 + w1 * v1a.y;
            azA = azA * c0 + w0 * v0b.x;  azB = azB * c1 + w1 * v1b.x;
            awA = awA * c0 + w0 * v0b.y;  awB = awB * c1 + w1 * v1b.y;
            mA = mn0; mB = mn1;
        }
        if (j < nload) {
            int s0 = __shfl_sync(0xffffffffu, sj, j);
            const uint2* kv0 = reinterpret_cast<const uint2*>(g_kv + (size_t)s0 * 256);
            uint2 k0u = kv0[lane];
            uint2 v0u = kv0[32 + lane];
            float2 k0a = __half22float2(*reinterpret_cast<__half2*>(&k0u.x));
            float2 k0b = __half22float2(*reinterpret_cast<__half2*>(&k0u.y));
            float p0 = qv.x * k0a.x + qv.y * k0a.y + qv.z * k0b.x + qv.w * k0b.y;
            p0 += __shfl_xor_sync(0xffffffffu, p0, 1);
            p0 += __shfl_xor_sync(0xffffffffu, p0, 2);
            float sc0 = p0 * 0.25f;
            float2 v0a = __half22float2(*reinterpret_cast<__half2*>(&v0u.x));
            float2 v0b = __half22float2(*reinterpret_cast<__half2*>(&v0u.y));
            float mn0 = fmaxf(mA, sc0);
            float c0 = __expf(mA - mn0), w0 = __expf(sc0 - mn0);
            sA = sA * c0 + w0;
            axA = axA * c0 + w0 * v0a.x;
            ayA = ayA * c0 + w0 * v0a.y;
            azA = azA * c0 + w0 * v0b.x;
            awA = awA * c0 + w0 * v0b.y;
            mA = mn0;
        }
        t += nload;
    }

    float m = fmaxf(mA, mB);
    float cA = __expf(mA - m), cB = __expf(mB - m);
    float sum = sA * cA + sB * cB;
    float ax = axA * cA + axB * cB;
    float ay = ayA * cA + ayB * cB;
    float az = azA * cA + azB * cB;
    float aw = awA * cA + awB * cB;

    float inv = 1.f / (sum + 1e-9f);
    float4 o;
    o.x = fmaxf(ax * inv, 0.f);
    o.y = fmaxf(ay * inv, 0.f);
    o.z = fmaxf(az * inv, 0.f);
    o.w = fmaxf(aw * inv, 0.f);
    *reinterpret_cast<float4*>(zout + (size_t)node * ldz + lane * 4) = o;
    if (WXT) {
        __half2 h0 = __floats2half2_rn(o.x, o.y);
        __half2 h1 = __floats2half2_rn(o.z, o.w);
        *reinterpret_cast<__half2*>(g_xt + (size_t)node * H_DIM + lane * 4)     = h0;
        *reinterpret_cast<__half2*>(g_xt + (size_t)node * H_DIM + lane * 4 + 2) = h1;
    }
}

// ---------------- kernels -------------------------------------------------------
#define PREPA_BLOCKS 6506
__global__ void k_prepA(const float* __restrict__ obs, const float* __restrict__ W1)
{
    int b = blockIdx.x, t = threadIdx.x;
    if (b < 6250) {
        int i = (b * 256 + t) * 4;
        if (i < N_NODES * OBS_DIM) {
            float4 v = *reinterpret_cast<const float4*>(obs + i);
            *reinterpret_cast<__half2*>(g_obsT + i)     = __floats2half2_rn(v.x, v.y);
            *reinterpret_cast<__half2*>(g_obsT + i + 2) = __floats2half2_rn(v.z, v.w);
        }
    } else {
        int i = (b - 6250) * 256 + t;
        int k = i >> 9, n = i & 511;
        g_W1t[n * 128 + k] = __float2half_rn(W1[i]);
    }
}

// L2: prepB front + gemm1 (full rows, 4 col tiles)
__global__ __launch_bounds__(256, 2)
void k_g1(const float* __restrict__ b1, WPtrs wp)
{
    extern __shared__ char sm[];
    if ((int)blockIdx.x < G1_EXTRA) { prepB_block_fn(blockIdx.x, wp); return; }
    gemm128_body<0>((int)blockIdx.x - G1_EXTRA, MT, 0,
                    g_obsT, OBS_DIM, g_W1t, b1, g_h1, ENC_H, N_NODES, sm);
}

// L3: scan front + g512 H1
__global__ __launch_bounds__(256, 2)
void k_g512_h1(const float* __restrict__ b2, float* __restrict__ out)
{
    extern __shared__ char sm[];
    if ((int)blockIdx.x < NB_SCAN) { scan_block_fn(blockIdx.x); return; }
    gemm512_body((int)blockIdx.x - NB_SCAN, 0, g_h1, g_W2t, b2,
                 out, OUT_LD, g_xt, H_DIM, N_NODES, sm);
}

// L4 (MIX A): g512 H2 + qkv1 H1
__global__ __launch_bounds__(256, 2)
void k_mixA(const float* __restrict__ b2, float* __restrict__ out)
{
    extern __shared__ char sm[];
    if ((int)blockIdx.x < MT_H2) {
        gemm512_body((int)blockIdx.x, SPLIT, g_h1, g_W2t, b2,
                     out, OUT_LD, g_xt, H_DIM, N_NODES, sm);
    } else {
        gemm128_body<2>((int)blockIdx.x - MT_H2, MT_H1, 0,
                        g_xt, H_DIM, g_Wt1, g_bp1, nullptr, 0, N_NODES, sm);
    }
}

// L5: scatter front + qkv1 H2
__global__ __launch_bounds__(256, 2)
void k_qkv1_h2(WPtrs wp)
{
    extern __shared__ char sm[];
    if ((int)blockIdx.x < NB_SCAT) { scatter_block_fn(blockIdx.x, wp); return; }
    gemm128_body<2>((int)blockIdx.x - NB_SCAT, MT_H2, SPLIT,
                    g_xt, H_DIM, g_Wt1, g_bp1, nullptr, 0, N_NODES, sm);
}

// L6 / L9: standalone GAT over node range
template <bool WXT>
__global__ void k_gat(float* __restrict__ zout, int ldz, int n0, int n1)
{
    int node = n0 + (int)blockIdx.x * 8 + (threadIdx.x >> 5);
    int lane = threadIdx.x & 31;
    if (node >= n1) return;
    gat_body<WXT>(node, lane, zout, ldz);
}

// L7 (MIX B): gat1 H2 + qkv2 H1
__global__ __launch_bounds__(256, 2)
void k_mixB(float* __restrict__ out)
{
    extern __shared__ char sm[];
    if ((int)blockIdx.x < GAT_H2_BLOCKS) {
        int node = SPLIT + (int)blockIdx.x * 8 + (threadIdx.x >> 5);
        int lane = threadIdx.x & 31;
        if (node < N_NODES) gat_body<true>(node, lane, out + H_DIM, OUT_LD);
        return;
    }
    gemm128_body<2>((int)blockIdx.x - GAT_H2_BLOCKS, MT_H1, 0,
                    g_xt, H_DIM, g_Wt2, g_bp2, nullptr, 0, N_NODES, sm);
}

// L8: qkv2 H2
__global__ __launch_bounds__(256, 2)
void k_qkv2_h2()
{
    extern __shared__ char sm[];
    gemm128_body<2>((int)blockIdx.x, MT_H2, SPLIT,
                    g_xt, H_DIM, g_Wt2, g_bp2, nullptr, 0, N_NODES, sm);
}

// ---------------- host ----------------------------------------------------------
extern "C" void kernel_launch(void* const* d_in, const int* in_sizes, int n_in,
                              void* d_out, int out_size)
{
    const float* obs = (const float*)d_in[0];
    const int*   src = (const int*)d_in[1];
    const int*   dst = (const int*)d_in[2];
    const float* W1  = (const float*)d_in[3];  const float* b1  = (const float*)d_in[4];
    const float* W2  = (const float*)d_in[5];  const float* b2  = (const float*)d_in[6];
    const float* Wq1 = (const float*)d_in[7];  const float* bq1 = (const float*)d_in[8];
    const float* Wk1 = (const float*)d_in[9];  const float* bk1 = (const float*)d_in[10];
    const float* Wv1 = (const float*)d_in[11]; const float* bv1 = (const float*)d_in[12];
    const float* Wq2 = (const float*)d_in[13]; const float* bq2 = (const float*)d_in[14];
    const float* Wk2 = (const float*)d_in[15]; const float* bk2 = (const float*)d_in[16];
    const float* Wv2 = (const float*)d_in[17]; const float* bv2 = (const float*)d_in[18];
    float* out = (float*)d_out;

    cudaFuncSetAttribute(k_g1,      cudaFuncAttributeMaxDynamicSharedMemorySize, K128_SMEM);
    cudaFuncSetAttribute(k_g512_h1, cudaFuncAttributeMaxDynamicSharedMemorySize, G512_SMEM);
    cudaFuncSetAttribute(k_mixA,    cudaFuncAttributeMaxDynamicSharedMemorySize, K128_SMEM);
    cudaFuncSetAttribute(k_qkv1_h2, cudaFuncAttributeMaxDynamicSharedMemorySize, K128_SMEM);
    cudaFuncSetAttribute(k_mixB,    cudaFuncAttributeMaxDynamicSharedMemorySize, K128_SMEM);
    cudaFuncSetAttribute(k_qkv2_h2, cudaFuncAttributeMaxDynamicSharedMemorySize, K128_SMEM);

    WPtrs wp;
    wp.W2 = W2;
    wp.Wq1 = Wq1; wp.bq1 = bq1; wp.Wk1 = Wk1; wp.bk1 = bk1; wp.Wv1 = Wv1; wp.bv1 = bv1;
    wp.Wq2 = Wq2; wp.bq2 = bq2; wp.Wk2 = Wk2; wp.bk2 = bk2; wp.Wv2 = Wv2; wp.bv2 = bv2;
    wp.src = src; wp.dst = dst;

    // L1: obs cvt + W1 pack
    k_prepA<<<PREPA_BLOCKS, 256>>>(obs, W1);
    // L2: prepB + gemm1
    k_g1<<<G1_EXTRA + MT * 4, 256, K128_SMEM>>>(b1, wp);
    // L3: scan + g512 H1
    k_g512_h1<<<NB_SCAN + MT_H1, 256, G512_SMEM>>>(b2, out);
    // L4: MIX A — g512 H2 + qkv1 H1
    k_mixA<<<MT_H2 + MT_H1 * 3, 256, K128_SMEM>>>(b2, out);
    // L5: scatter + qkv1 H2
    k_qkv1_h2<<<NB_SCAT + MT_H2 * 3, 256, K128_SMEM>>>(wp);
    // L6: gat1 H1
    k_gat<true><<<GAT_H1_BLOCKS, 256>>>(out + H_DIM, OUT_LD, 0, SPLIT);
    // L7: MIX B — gat1 H2 + qkv2 H1
    k_mixB<<<GAT_H2_BLOCKS + MT_H1 * 3, 256, K128_SMEM>>>(out);
    // L8: qkv2 H2
    k_qkv2_h2<<<MT_H2 * 3, 256, K128_SMEM>>>();
    // L9: gat2 full
    k_gat<false><<<GAT_FULL_BLOCKS, 256>>>(out + 2 * H_DIM, OUT_LD, 0, N_NODES);
}

// round 16
// speedup vs baseline: 1.1633x; 1.1633x over previous
#include <cuda_runtime.h>
#include <cuda_fp16.h>
#include <cstdint>
#include <math.h>

#define N_NODES 50000
#define N_EDGES 800000
#define OBS_DIM 128
#define H_DIM   128
#define ENC_H   512
#define OUT_LD  384
#define NB_SCAN 196   // ceil(50000/256)
#define NB_SCAT 3125  // ceil(800000/256)
#define MT      391   // ceil(50000/128)

// ---------------- scratch ------------------------------------------------------
__device__ __half   g_h1[(size_t)N_NODES * ENC_H];
__device__ __half   g_xt[(size_t)N_NODES * H_DIM];
__device__ float    g_q [(size_t)N_NODES * H_DIM];
__device__ __half   g_kv[(size_t)N_NODES * 256];
__device__ __half   g_W1t[512 * 128];
__device__ __half   g_W2t[128 * 512];
__device__ __half   g_Wt1[384 * 128];
__device__ __half   g_Wt2[384 * 128];
__device__ float    g_bp1[384];
__device__ float    g_bp2[384];
__device__ int      g_deg[N_NODES];
__device__ int      g_off[N_NODES + 1];
__device__ int      g_pos[N_NODES];
__device__ int      g_srcs[N_EDGES];
__device__ unsigned long long g_lb[NB_SCAN];

#define LB_PARTIAL (1ull << 62)
#define LB_PREFIX  (2ull << 62)
#define LB_MASK    (3ull << 62)

// ---------------- helpers ------------------------------------------------------
__device__ __forceinline__ uint32_t smem_u32(const void* p) {
    uint32_t a;
    asm("{ .reg .u64 t; cvta.to.shared.u64 t, %1; cvt.u32.u64 %0, t; }" : "=r"(a) : "l"(p));
    return a;
}
__device__ __forceinline__ void cp16(uint32_t sm_addr, const void* g, int nbytes) {
    asm volatile("cp.async.cg.shared.global [%0], [%1], 16, %2;"
                 :: "r"(sm_addr), "l"(g), "r"(nbytes) : "memory");
}
__device__ __forceinline__ void cp_commit() {
    asm volatile("cp.async.commit_group;" ::: "memory");
}
template <int N>
__device__ __forceinline__ void cp_wait() {
    asm volatile("cp.async.wait_group %0;" :: "n"(N) : "memory");
}
__device__ __forceinline__ void mma_f16(float* c, const uint32_t* a, const uint32_t* b) {
    asm volatile(
        "mma.sync.aligned.m16n8k16.row.col.f32.f16.f16.f32 "
        "{%0,%1,%2,%3}, {%4,%5,%6,%7}, {%8,%9}, {%0,%1,%2,%3};\n"
        : "+f"(c[0]), "+f"(c[1]), "+f"(c[2]), "+f"(c[3])
        : "r"(a[0]), "r"(a[1]), "r"(a[2]), "r"(a[3]), "r"(b[0]), "r"(b[1]));
}
__device__ __forceinline__ void ldsm_x4(uint32_t& r0, uint32_t& r1, uint32_t& r2, uint32_t& r3,
                                        uint32_t addr) {
    asm volatile("ldmatrix.sync.aligned.m8n8.x4.shared.b16 {%0,%1,%2,%3}, [%4];"
                 : "=r"(r0), "=r"(r1), "=r"(r2), "=r"(r3) : "r"(addr));
}

// ---------------- CSR device blocks ---------------------------------------------
__device__ __forceinline__ int block_excl_scan(int v, int tid) {
    int lane = tid & 31, w = tid >> 5;
    int x = v;
    #pragma unroll
    for (int d = 1; d < 32; d <<= 1) {
        int t = __shfl_up_sync(0xffffffffu, x, d);
        if (lane >= d) x += t;
    }
    __shared__ int ws[8];
    if (lane == 31) ws[w] = x;
    __syncthreads();
    if (w == 0) {
        int y = (lane < 8) ? ws[lane] : 0;
        #pragma unroll
        for (int d = 1; d < 8; d <<= 1) {
            int t = __shfl_up_sync(0xffffffffu, y, d);
            if (lane >= d) y += t;
        }
        if (lane < 8) ws[lane] = y;
    }
    __syncthreads();
    return x - v + ((w > 0) ? ws[w - 1] : 0);
}

__device__ __forceinline__ void scan_block_fn(int b) {
    int tid = threadIdx.x;
    int i = b * 256 + tid;
    int v = (i < N_NODES) ? g_deg[i] : 0;
    if (i < N_NODES) g_deg[i] = 0;
    int excl = block_excl_scan(v, tid);
    __shared__ int s_prefix;

    if (tid == 255) {
        unsigned long long agg = (unsigned long long)(excl + v);
        if (b == 0) atomicExch(&g_lb[0], LB_PREFIX | agg);
        else        atomicExch(&g_lb[b], LB_PARTIAL | agg);
    }
    if (tid == 0) {
        if (b == 0) s_prefix = 0;
        else {
            long long running = 0;
            int p = b - 1;
            for (;;) {
                unsigned long long x = atomicAdd(&g_lb[p], 0ull);
                unsigned long long st = x & LB_MASK;
                if (st == LB_PREFIX)  { running += (long long)(x & ~LB_MASK); break; }
                if (st == LB_PARTIAL) { running += (long long)(x & ~LB_MASK); p--; }
            }
            s_prefix = (int)running;
        }
    }
    __syncthreads();
    int pre = s_prefix;
    if (b > 0 && tid == 255)
        atomicExch(&g_lb[b], LB_PREFIX | (unsigned long long)(pre + excl + v));
    if (i < N_NODES) {
        int o = pre + excl;
        g_off[i] = o;
        g_pos[i] = o;
    }
    if (b == NB_SCAN - 1 && tid == 255) g_off[N_NODES] = pre + excl + v;
}

__device__ __forceinline__ void scatter_block_fn(int b, const int* __restrict__ src,
                                                 const int* __restrict__ dst) {
    int e = b * 256 + threadIdx.x;
    if (e < NB_SCAN) g_lb[e] = 0ull;
    if (e < N_EDGES) {
        int d = dst[e];
        int idx = atomicAdd(&g_pos[d], 1);
        g_srcs[idx] = src[e];
    }
}

// ---------------- K=128 GEMM kernels (128x128 tile, single-stage) ----------------
#define K128_SROW 272
#define K128_OP   (128 * K128_SROW)     // 34816
#define K128_SMEM (2 * K128_OP)         // 69632

// shared mainloop + epilogue (A already staged, B cp.async outstanding)
template <int MODE>
__device__ __forceinline__ void gemm128_mainloop(
    uint32_t sbase, int rowBase, int colBase,
    const float* __restrict__ bias,
    __half* __restrict__ Ct, int ldct, int M)
{
    const int tid  = threadIdx.x;
    const int lane = tid & 31;
    const int w    = tid >> 5;
    const int gid  = lane >> 2;
    const int tig  = lane & 3;
    const int warpM = w >> 2;
    const int warpN = w & 3;

    const int sub = lane >> 3, lr = lane & 7;
    const uint32_t aOff = (uint32_t)(warpM * 64 + ((sub & 1) << 3) + lr) * K128_SROW
                        + ((uint32_t)(sub >> 1) << 4);
    const uint32_t bOff = K128_OP
                        + (uint32_t)(warpN * 32 + ((sub >> 1) << 3) + lr) * K128_SROW
                        + ((uint32_t)(sub & 1) << 4);

    float acc[4][4][4];
    #pragma unroll
    for (int mt = 0; mt < 4; mt++)
        #pragma unroll
        for (int nt = 0; nt < 4; nt++)
            #pragma unroll
            for (int j = 0; j < 4; j++) acc[mt][nt][j] = 0.f;

    cp_wait<0>();
    __syncthreads();

    #pragma unroll
    for (int kk = 0; kk < 8; kk++) {
        const uint32_t kb = (uint32_t)kk << 5;
        uint32_t af[4][4], bf[4][2];
        #pragma unroll
        for (int mt = 0; mt < 4; mt++)
            ldsm_x4(af[mt][0], af[mt][1], af[mt][2], af[mt][3],
                    sbase + aOff + (uint32_t)(mt * 16) * K128_SROW + kb);
        #pragma unroll
        for (int p = 0; p < 2; p++)
            ldsm_x4(bf[2 * p][0], bf[2 * p][1], bf[2 * p + 1][0], bf[2 * p + 1][1],
                    sbase + bOff + (uint32_t)(p * 16) * K128_SROW + kb);
        #pragma unroll
        for (int mt = 0; mt < 4; mt++)
            #pragma unroll
            for (int nt = 0; nt < 4; nt++)
                mma_f16(acc[mt][nt], af[mt], bf[nt]);
    }

    #pragma unroll
    for (int mt = 0; mt < 4; mt++) {
        int r0 = rowBase + warpM * 64 + mt * 16 + gid;
        #pragma unroll
        for (int nt = 0; nt < 4; nt++) {
            int cc = colBase + warpN * 32 + nt * 8 + tig * 2;
            float2 bi = *reinterpret_cast<const float2*>(bias + cc);
            #pragma unroll
            for (int h = 0; h < 2; h++) {
                int r = r0 + h * 8;
                if (r < M) {
                    float ox = acc[mt][nt][h * 2 + 0] + bi.x;
                    float oy = acc[mt][nt][h * 2 + 1] + bi.y;
                    if (MODE == 0) {
                        ox = fmaxf(ox, 0.f); oy = fmaxf(oy, 0.f);
                        *reinterpret_cast<__half2*>(Ct + (size_t)r * ldct + cc) =
                            __floats2half2_rn(ox, oy);
                    } else {
                        if (colBase == 0) {
                            *reinterpret_cast<float2*>(g_q + (size_t)r * H_DIM + cc) =
                                make_float2(ox, oy);
                        } else {
                            *reinterpret_cast<__half2*>(g_kv + (size_t)r * 256 + (cc - 128)) =
                                __floats2half2_rn(ox, oy);
                        }
                    }
                }
            }
        }
    }
}

// gemm1: A = obs fp32 (LDG + cvt + STS), B = W1t fp16 via cp.async; scan at tail
__global__ __launch_bounds__(256, 2)
void k_g1(const float* __restrict__ obs, const float* __restrict__ bias,
          int nGemm)
{
    if ((int)blockIdx.x >= nGemm) { scan_block_fn(blockIdx.x - nGemm); return; }
    extern __shared__ char sm[];
    const uint32_t sbase = smem_u32(sm);
    const int tid = threadIdx.x;
    const int rowBase = ((int)blockIdx.x % MT) * 128;
    const int colBase = ((int)blockIdx.x / MT) * 128;

    // B via cp.async (issue first so it overlaps the A LDG latency)
    #pragma unroll
    for (int p = 0; p < 8; p++) {
        int idx = tid + (p << 8);
        int row = idx >> 4;
        int ch  = idx & 15;
        cp16(sbase + K128_OP + row * K128_SROW + (ch << 4),
             g_W1t + (size_t)(colBase + row) * 128 + ch * 8, 16);
    }
    cp_commit();

    // A: fp32 obs -> fp16 smem. 2048 chunks of 8 halves (8/thread).
    #pragma unroll
    for (int p = 0; p < 8; p++) {
        int idx = tid + (p << 8);
        int row = idx >> 4;
        int ch  = idx & 15;
        int gr = rowBase + row;
        float4 a0 = make_float4(0.f, 0.f, 0.f, 0.f), a1 = a0;
        if (gr < N_NODES) {
            const float4* ga = reinterpret_cast<const float4*>(obs + (size_t)gr * OBS_DIM + ch * 8);
            a0 = ga[0]; a1 = ga[1];
        }
        __half2 h0 = __floats2half2_rn(a0.x, a0.y);
        __half2 h1 = __floats2half2_rn(a0.z, a0.w);
        __half2 h2 = __floats2half2_rn(a1.x, a1.y);
        __half2 h3 = __floats2half2_rn(a1.z, a1.w);
        uint4 u;
        u.x = *reinterpret_cast<uint32_t*>(&h0);
        u.y = *reinterpret_cast<uint32_t*>(&h1);
        u.z = *reinterpret_cast<uint32_t*>(&h2);
        u.w = *reinterpret_cast<uint32_t*>(&h3);
        *reinterpret_cast<uint4*>(sm + row * K128_SROW + (ch << 4)) = u;
    }

    gemm128_mainloop<0>(sbase, rowBase, colBase, bias, g_h1, ENC_H, N_NODES);
}

// qkv GEMMs: A,B fp16 via cp.async. EXTRA: 0 none, 2 scatter at tail.
template <int EXTRA>
__global__ __launch_bounds__(256, 2)
void k_qkv(const __half* __restrict__ A, const __half* __restrict__ Bt,
           const float* __restrict__ bias, int nGemm,
           const int* __restrict__ src, const int* __restrict__ dst)
{
    if (EXTRA != 0 && (int)blockIdx.x >= nGemm) {
        scatter_block_fn(blockIdx.x - nGemm, src, dst);
        return;
    }
    extern __shared__ char sm[];
    const uint32_t sbase = smem_u32(sm);
    const int tid = threadIdx.x;
    const int rowBase = ((int)blockIdx.x % MT) * 128;
    const int colBase = ((int)blockIdx.x / MT) * 128;

    #pragma unroll
    for (int p = 0; p < 8; p++) {
        int idx = tid + (p << 8);
        int row = idx >> 4;
        int ch  = idx & 15;
        uint32_t off = row * K128_SROW + (ch << 4);
        int gr = rowBase + row;
        int okA = (gr < N_NODES) ? 16 : 0;
        cp16(sbase + off, A + (size_t)(okA ? gr : 0) * H_DIM + ch * 8, okA);
        cp16(sbase + K128_OP + off, Bt + (size_t)(colBase + row) * 128 + ch * 8, 16);
    }
    cp_commit();

    gemm128_mainloop<2>(sbase, rowBase, colBase, bias, nullptr, 0, N_NODES);
}

// ---------------- pipelined FP16 GEMM (K=512) -----------------------------------
#define SROW_B   80
#define ST_OP_B  (128 * SROW_B)
#define ST_BYTES (2 * ST_OP_B)
#define GEMM_SMEM (3 * ST_BYTES)

__device__ __forceinline__ void load_stage(
    uint32_t sbase, int stage, const __half* __restrict__ A,
    const __half* __restrict__ Bt, int rowBase, int k0, int tid)
{
    uint32_t st = sbase + stage * ST_BYTES;
    #pragma unroll
    for (int p = 0; p < 2; p++) {
        int idx = tid + (p << 8);
        int row = idx >> 2;
        int kc  = idx & 3;
        uint32_t off = row * SROW_B + kc * 16;
        int gr = rowBase + row;
        int okA = (gr < N_NODES) ? 16 : 0;
        cp16(st + off, A + (size_t)(okA ? gr : 0) * ENC_H + k0 + kc * 8, okA);
        cp16(st + ST_OP_B + off, Bt + (size_t)row * ENC_H + k0 + kc * 8, 16);
    }
    cp_commit();
}

__global__ __launch_bounds__(256, 2)
void gemm_k512(const __half* __restrict__ A, const __half* __restrict__ Bt,
               const float* __restrict__ bias,
               float* __restrict__ C, int ldc,
               __half* __restrict__ Ct, int ldct)
{
    extern __shared__ char sm[];
    const uint32_t sbase = smem_u32(sm);
    const int tid  = threadIdx.x;
    const int lane = tid & 31;
    const int w    = tid >> 5;
    const int gid  = lane >> 2;
    const int tig  = lane & 3;
    const int warpM = w >> 2;
    const int warpN = w & 3;
    const int rowBase = blockIdx.x * 128;
    const int nCh = ENC_H >> 5;

    const int sub = lane >> 3, lr = lane & 7;
    const uint32_t aOff = (uint32_t)(warpM * 64 + ((sub & 1) << 3) + lr) * SROW_B
                        + ((uint32_t)(sub >> 1) << 4);
    const uint32_t bOff = ST_OP_B
                        + (uint32_t)(warpN * 32 + ((sub >> 1) << 3) + lr) * SROW_B
                        + ((uint32_t)(sub & 1) << 4);

    float acc[4][4][4];
    #pragma unroll
    for (int mt = 0; mt < 4; mt++)
        #pragma unroll
        for (int nt = 0; nt < 4; nt++)
            #pragma unroll
            for (int j = 0; j < 4; j++) acc[mt][nt][j] = 0.f;

    load_stage(sbase, 0, A, Bt, rowBase, 0, tid);
    load_stage(sbase, 1, A, Bt, rowBase, 32, tid);

    int stage = 0;
    #pragma unroll 1
    for (int c = 0; c < nCh; c++) {
        if (c + 1 < nCh) cp_wait<1>(); else cp_wait<0>();
        __syncthreads();
        if (c + 2 < nCh) {
            int ns = stage + 2; if (ns >= 3) ns -= 3;
            load_stage(sbase, ns, A, Bt, rowBase, (c + 2) << 5, tid);
        }
        const uint32_t stA = sbase + stage * ST_BYTES;
        #pragma unroll
        for (int kk = 0; kk < 2; kk++) {
            const uint32_t kb = (uint32_t)kk << 5;
            uint32_t af[4][4], bf[4][2];
            #pragma unroll
            for (int mt = 0; mt < 4; mt++)
                ldsm_x4(af[mt][0], af[mt][1], af[mt][2], af[mt][3],
                        stA + aOff + (uint32_t)(mt * 16) * SROW_B + kb);
            #pragma unroll
            for (int p = 0; p < 2; p++)
                ldsm_x4(bf[2 * p][0], bf[2 * p][1], bf[2 * p + 1][0], bf[2 * p + 1][1],
                        stA + bOff + (uint32_t)(p * 16) * SROW_B + kb);
            #pragma unroll
            for (int mt = 0; mt < 4; mt++)
                #pragma unroll
                for (int nt = 0; nt < 4; nt++)
                    mma_f16(acc[mt][nt], af[mt], bf[nt]);
        }
        stage++; if (stage >= 3) stage = 0;
    }

    #pragma unroll
    for (int mt = 0; mt < 4; mt++) {
        int r0 = rowBase + warpM * 64 + mt * 16 + gid;
        #pragma unroll
        for (int nt = 0; nt < 4; nt++) {
            int cc = warpN * 32 + nt * 8 + tig * 2;
            float2 bi = *reinterpret_cast<const float2*>(bias + cc);
            #pragma unroll
            for (int h = 0; h < 2; h++) {
                int r = r0 + h * 8;
                if (r < N_NODES) {
                    float ox = fmaxf(acc[mt][nt][h * 2 + 0] + bi.x, 0.f);
                    float oy = fmaxf(acc[mt][nt][h * 2 + 1] + bi.y, 0.f);
                    *reinterpret_cast<float2*>(C + (size_t)r * ldc + cc) = make_float2(ox, oy);
                    *reinterpret_cast<__half2*>(Ct + (size_t)r * ldct + cc) =
                        __floats2half2_rn(ox, oy);
                }
            }
        }
    }
}

// ---------------- prep: weight packs + edge count (no obs cvt) ------------------
#define PREP_BLOCKS 3765   // 256 W1 + 256 W2 + 64 qkv1 + 64 qkv2 + 3125 count

__global__ void k_prep(const int* __restrict__ dst,
                       const float* __restrict__ W1, const float* __restrict__ W2,
                       const float* __restrict__ Wq1, const float* __restrict__ bq1,
                       const float* __restrict__ Wk1, const float* __restrict__ bk1,
                       const float* __restrict__ Wv1, const float* __restrict__ bv1,
                       const float* __restrict__ Wq2, const float* __restrict__ bq2,
                       const float* __restrict__ Wk2, const float* __restrict__ bk2,
                       const float* __restrict__ Wv2, const float* __restrict__ bv2)
{
    int b = blockIdx.x, t = threadIdx.x;
    if (b < 256) {
        int i = b * 256 + t;                // W1: [128,512] -> g_W1t[n][128]
        int k = i >> 9, n = i & 511;
        g_W1t[n * 128 + k] = __float2half_rn(W1[i]);
    } else if (b < 512) {
        int i = (b - 256) * 256 + t;        // W2: [512,128] -> g_W2t[n][512]
        int k = i >> 7, n = i & 127;
        g_W2t[n * 512 + k] = __float2half_rn(W2[i]);
    } else if (b < 576) {
        int i = (b - 512) * 256 + t;        // qkv1
        int k = i >> 7, n = i & 127;
        g_Wt1[n * 128 + k]         = __float2half_rn(Wq1[i]);
        g_Wt1[(n + 128) * 128 + k] = __float2half_rn(Wk1[i]);
        g_Wt1[(n + 256) * 128 + k] = __float2half_rn(Wv1[i]);
        if (i < 128) { g_bp1[i] = bq1[i]; g_bp1[128 + i] = bk1[i]; g_bp1[256 + i] = bv1[i]; }
    } else if (b < 640) {
        int i = (b - 576) * 256 + t;        // qkv2
        int k = i >> 7, n = i & 127;
        g_Wt2[n * 128 + k]         = __float2half_rn(Wq2[i]);
        g_Wt2[(n + 128) * 128 + k] = __float2half_rn(Wk2[i]);
        g_Wt2[(n + 256) * 128 + k] = __float2half_rn(Wv2[i]);
        if (i < 128) { g_bp2[i] = bq2[i]; g_bp2[128 + i] = bk2[i]; g_bp2[256 + i] = bv2[i]; }
    } else {
        int e = (b - 640) * 256 + t;        // edge degree count (g_deg pre-zeroed)
        if (e < N_EDGES) atomicAdd(&g_deg[dst[e]], 1);
    }
}

// ---------------- GAT: one warp per dst node, fp16 k/v, dual-state softmax ------
template <bool WXT>
__global__ void k_gat(float* __restrict__ zout, int ldz)
{
    int node = (blockIdx.x * blockDim.x + threadIdx.x) >> 5;
    int lane = threadIdx.x & 31;
    if (node >= N_NODES) return;

    const float4 qv = *reinterpret_cast<const float4*>(g_q + (size_t)node * H_DIM + lane * 4);

    float mA = -1e30f, sA = 0.f, axA = 0.f, ayA = 0.f, azA = 0.f, awA = 0.f;
    float mB = -1e30f, sB = 0.f, axB = 0.f, ayB = 0.f, azB = 0.f, awB = 0.f;

    int t = g_off[node], end = g_off[node + 1];
    while (t < end) {
        int nload = min(32, end - t);
        int sj = (lane < nload) ? __ldg(&g_srcs[t + lane]) : 0;
        int j = 0;
        for (; j + 1 < nload; j += 2) {
            int s0 = __shfl_sync(0xffffffffu, sj, j);
            int s1 = __shfl_sync(0xffffffffu, sj, j + 1);
            const uint2* kv0 = reinterpret_cast<const uint2*>(g_kv + (size_t)s0 * 256);
            const uint2* kv1 = reinterpret_cast<const uint2*>(g_kv + (size_t)s1 * 256);
            uint2 k0u = kv0[lane],      k1u = kv1[lane];
            uint2 v0u = kv0[32 + lane], v1u = kv1[32 + lane];

            float2 k0a = __half22float2(*reinterpret_cast<__half2*>(&k0u.x));
            float2 k0b = __half22float2(*reinterpret_cast<__half2*>(&k0u.y));
            float2 k1a = __half22float2(*reinterpret_cast<__half2*>(&k1u.x));
            float2 k1b = __half22float2(*reinterpret_cast<__half2*>(&k1u.y));

            float p0 = qv.x * k0a.x + qv.y * k0a.y + qv.z * k0b.x + qv.w * k0b.y;
            float p1 = qv.x * k1a.x + qv.y * k1a.y + qv.z * k1b.x + qv.w * k1b.y;
            p0 += __shfl_xor_sync(0xffffffffu, p0, 1);
            p1 += __shfl_xor_sync(0xffffffffu, p1, 1);
            p0 += __shfl_xor_sync(0xffffffffu, p0, 2);
            p1 += __shfl_xor_sync(0xffffffffu, p1, 2);
            float sc0 = p0 * 0.25f, sc1 = p1 * 0.25f;

            float2 v0a = __half22float2(*reinterpret_cast<__half2*>(&v0u.x));
            float2 v0b = __half22float2(*reinterpret_cast<__half2*>(&v0u.y));
            float2 v1a = __half22float2(*reinterpret_cast<__half2*>(&v1u.x));
            float2 v1b = __half22float2(*reinterpret_cast<__half2*>(&v1u.y));

            float mn0 = fmaxf(mA, sc0);
            float mn1 = fmaxf(mB, sc1);
            float c0 = __expf(mA - mn0), w0 = __expf(sc0 - mn0);
            float c1 = __expf(mB - mn1), w1 = __expf(sc1 - mn1);
            sA = sA * c0 + w0;
            sB = sB * c1 + w1;
            axA = axA * c0 + w0 * v0a.x;  axB = axB * c1 + w1 * v1a.x;
            ayA = ayA * c0 + w0 * v0a.y;  ayB = ayB * c1 + w1 * v1a.y;
            azA = azA * c0 + w0 * v0b.x;  azB = azB * c1 + w1 * v1b.x;
            awA = awA * c0 + w0 * v0b.y;  awB = awB * c1 + w1 * v1b.y;
            mA = mn0; mB = mn1;
        }
        if (j < nload) {
            int s0 = __shfl_sync(0xffffffffu, sj, j);
            const uint2* kv0 = reinterpret_cast<const uint2*>(g_kv + (size_t)s0 * 256);
            uint2 k0u = kv0[lane];
            uint2 v0u = kv0[32 + lane];
            float2 k0a = __half22float2(*reinterpret_cast<__half2*>(&k0u.x));
            float2 k0b = __half22float2(*reinterpret_cast<__half2*>(&k0u.y));
            float p0 = qv.x * k0a.x + qv.y * k0a.y + qv.z * k0b.x + qv.w * k0b.y;
            p0 += __shfl_xor_sync(0xffffffffu, p0, 1);
            p0 += __shfl_xor_sync(0xffffffffu, p0, 2);
            float sc0 = p0 * 0.25f;
            float2 v0a = __half22float2(*reinterpret_cast<__half2*>(&v0u.x));
            float2 v0b = __half22float2(*reinterpret_cast<__half2*>(&v0u.y));
            float mn0 = fmaxf(mA, sc0);
            float c0 = __expf(mA - mn0), w0 = __expf(sc0 - mn0);
            sA = sA * c0 + w0;
            axA = axA * c0 + w0 * v0a.x;
            ayA = ayA * c0 + w0 * v0a.y;
            azA = azA * c0 + w0 * v0b.x;
            awA = awA * c0 + w0 * v0b.y;
            mA = mn0;
        }
        t += nload;
    }

    float m = fmaxf(mA, mB);
    float cA = __expf(mA - m), cB = __expf(mB - m);
    float sum = sA * cA + sB * cB;
    float ax = axA * cA + axB * cB;
    float ay = ayA * cA + ayB * cB;
    float az = azA * cA + azB * cB;
    float aw = awA * cA + awB * cB;

    float inv = 1.f / (sum + 1e-9f);
    float4 o;
    o.x = fmaxf(ax * inv, 0.f);
    o.y = fmaxf(ay * inv, 0.f);
    o.z = fmaxf(az * inv, 0.f);
    o.w = fmaxf(aw * inv, 0.f);
    *reinterpret_cast<float4*>(zout + (size_t)node * ldz + lane * 4) = o;
    if (WXT) {
        __half2 h0 = __floats2half2_rn(o.x, o.y);
        __half2 h1 = __floats2half2_rn(o.z, o.w);
        *reinterpret_cast<__half2*>(g_xt + (size_t)node * H_DIM + lane * 4)     = h0;
        *reinterpret_cast<__half2*>(g_xt + (size_t)node * H_DIM + lane * 4 + 2) = h1;
    }
}

// ---------------- host ----------------------------------------------------------
extern "C" void kernel_launch(void* const* d_in, const int* in_sizes, int n_in,
                              void* d_out, int out_size)
{
    const float* obs = (const float*)d_in[0];
    const int*   src = (const int*)d_in[1];
    const int*   dst = (const int*)d_in[2];
    const float* W1  = (const float*)d_in[3];  const float* b1  = (const float*)d_in[4];
    const float* W2  = (const float*)d_in[5];  const float* b2  = (const float*)d_in[6];
    const float* Wq1 = (const float*)d_in[7];  const float* bq1 = (const float*)d_in[8];
    const float* Wk1 = (const float*)d_in[9];  const float* bk1 = (const float*)d_in[10];
    const float* Wv1 = (const float*)d_in[11]; const float* bv1 = (const float*)d_in[12];
    const float* Wq2 = (const float*)d_in[13]; const float* bq2 = (const float*)d_in[14];
    const float* Wk2 = (const float*)d_in[15]; const float* bk2 = (const float*)d_in[16];
    const float* Wv2 = (const float*)d_in[17]; const float* bv2 = (const float*)d_in[18];
    float* out = (float*)d_out;

    __half *p_h1, *p_xt, *p_W2t, *p_Wt1, *p_Wt2;
    float *p_bp1, *p_bp2;
    cudaGetSymbolAddress((void**)&p_h1,  g_h1);
    cudaGetSymbolAddress((void**)&p_xt,  g_xt);
    cudaGetSymbolAddress((void**)&p_W2t, g_W2t);
    cudaGetSymbolAddress((void**)&p_Wt1, g_Wt1);
    cudaGetSymbolAddress((void**)&p_Wt2, g_Wt2);
    cudaGetSymbolAddress((void**)&p_bp1, g_bp1);
    cudaGetSymbolAddress((void**)&p_bp2, g_bp2);

    cudaFuncSetAttribute(k_g1,     cudaFuncAttributeMaxDynamicSharedMemorySize, K128_SMEM);
    cudaFuncSetAttribute(k_qkv<2>, cudaFuncAttributeMaxDynamicSharedMemorySize, K128_SMEM);
    cudaFuncSetAttribute(k_qkv<0>, cudaFuncAttributeMaxDynamicSharedMemorySize, K128_SMEM);
    cudaFuncSetAttribute(gemm_k512, cudaFuncAttributeMaxDynamicSharedMemorySize, GEMM_SMEM);

    // prep: weight packs + edge-degree count (obs cvt eliminated)
    k_prep<<<PREP_BLOCKS, 256>>>(dst, W1, W2,
                                 Wq1, bq1, Wk1, bk1, Wv1, bv1,
                                 Wq2, bq2, Wk2, bk2, Wv2, bv2);

    // MLP layer 1 (fp32 A direct) + scan at tail
    k_g1<<<MT * 4 + NB_SCAN, 256, K128_SMEM>>>(obs, b1, MT * 4);

    // MLP layer 2 (K=512)
    gemm_k512<<<MT, 256, GEMM_SMEM>>>(p_h1, p_W2t, b2, out + 0, OUT_LD, p_xt, H_DIM);

    // QKV layer 1 + scatter at tail
    k_qkv<2><<<MT * 3 + NB_SCAT, 256, K128_SMEM>>>(p_xt, p_Wt1, p_bp1, MT * 3, src, dst);
    k_gat<true><<<(N_NODES * 32 + 255) / 256, 256>>>(out + H_DIM, OUT_LD);

    // QKV layer 2
    k_qkv<0><<<MT * 3, 256, K128_SMEM>>>(p_xt, p_Wt2, p_bp2, MT * 3, nullptr, nullptr);
    k_gat<false><<<(N_NODES * 32 + 255) / 256, 256>>>(out + 2 * H_DIM, OUT_LD);
}